// round 13
// baseline (speedup 1.0000x reference)
#include <cuda_runtime.h>
#include <cuda_fp16.h>
#include <math.h>

#define BSZ 2
#define TSEQ 2048
#define DMODEL 1024
#define NH 16
#define DK 64
#define BT (BSZ * TSEQ)          // 4096
#define GEMM_KT 16               // K=1024 / BK=64

// ---------------- scratch ----------------
__device__ __half g_xh[BT * DMODEL];
__device__ __half g_wqkvT[3 * DMODEL * DMODEL];           // [3072][1024]
__device__ __half g_woutT[DMODEL * DMODEL];               // [1024][1024]
__device__ __half g_qh[BSZ * NH * TSEQ * DK];             // [bh][t][d]
__device__ __half g_kh[BSZ * NH * TSEQ * DK];
__device__ __half g_vh[BSZ * NH * TSEQ * DK];
__device__ __half g_attn[BT * DMODEL];
__device__ float2 g_rope[TSEQ * 32];                      // (cos,sin) per (t, d2)

// swizzle: 64-half rows (128B), 16B chunks
__device__ __forceinline__ unsigned swz(unsigned row, unsigned chunk) {
    return row * 128u + ((chunk ^ (row & 7u)) << 4);
}
__device__ __forceinline__ unsigned smaddr(const void* p) {
    return (unsigned)__cvta_generic_to_shared(p);
}
__device__ __forceinline__ void cp16(unsigned s, const void* g) {
    asm volatile("cp.async.cg.shared.global [%0], [%1], 16;\n" :: "r"(s), "l"(g));
}
__device__ __forceinline__ void cp_commit() { asm volatile("cp.async.commit_group;\n" ::); }
__device__ __forceinline__ void cp_wait0() { asm volatile("cp.async.wait_group 0;\n" ::); }
__device__ __forceinline__ void cp_wait1() { asm volatile("cp.async.wait_group 1;\n" ::); }

__device__ __forceinline__ void ldsm4(unsigned* r, unsigned a) {
    asm volatile("ldmatrix.sync.aligned.m8n8.x4.shared.b16 {%0,%1,%2,%3}, [%4];\n"
                 : "=r"(r[0]), "=r"(r[1]), "=r"(r[2]), "=r"(r[3]) : "r"(a));
}
__device__ __forceinline__ void ldsm4t(unsigned* r, unsigned a) {
    asm volatile("ldmatrix.sync.aligned.m8n8.x4.trans.shared.b16 {%0,%1,%2,%3}, [%4];\n"
                 : "=r"(r[0]), "=r"(r[1]), "=r"(r[2]), "=r"(r[3]) : "r"(a));
}
__device__ __forceinline__ void mma_f16(float* c, unsigned a0, unsigned a1,
                                        unsigned a2, unsigned a3,
                                        unsigned b0, unsigned b1) {
    asm volatile(
        "mma.sync.aligned.m16n8k16.row.col.f32.f16.f16.f32 "
        "{%0,%1,%2,%3}, {%4,%5,%6,%7}, {%8,%9}, {%0,%1,%2,%3};\n"
        : "+f"(c[0]), "+f"(c[1]), "+f"(c[2]), "+f"(c[3])
        : "r"(a0), "r"(a1), "r"(a2), "r"(a3), "r"(b0), "r"(b1));
}
// fp16-accumulator variant: c = 2 x b32 (each a half2)
__device__ __forceinline__ void mma_h16(unsigned* c, unsigned a0, unsigned a1,
                                        unsigned a2, unsigned a3,
                                        unsigned b0, unsigned b1) {
    asm volatile(
        "mma.sync.aligned.m16n8k16.row.col.f16.f16.f16.f16 "
        "{%0,%1}, {%2,%3,%4,%5}, {%6,%7}, {%0,%1};\n"
        : "+r"(c[0]), "+r"(c[1])
        : "r"(a0), "r"(a1), "r"(a2), "r"(a3), "r"(b0), "r"(b1));
}
__device__ __forceinline__ unsigned pack_h2(float a, float b) {
    __half2 h = __floats2half2_rn(a, b);
    return *reinterpret_cast<unsigned*>(&h);
}

// ---------------------------------------------------------------------------
// Fused prep: one launch does cast_x + rope table + both weight transposes.
// ---------------------------------------------------------------------------
__global__ __launch_bounds__(256)
void prep_kernel(const float* __restrict__ x,
                 const float* __restrict__ W_qkv,
                 const float* __restrict__ W_out)
{
    __shared__ float tile[64][65];
    const int bid = blockIdx.x;
    const int tid = threadIdx.x;

    if (bid < 4096) {                      // ---- cast x ----
        int i = bid * 256 + tid;           // float4 index
        float4 v = ((const float4*)x)[i];
        __half2 h0 = __floats2half2_rn(v.x, v.y);
        __half2 h1 = __floats2half2_rn(v.z, v.w);
        ((uint2*)g_xh)[i] = make_uint2(*(unsigned*)&h0, *(unsigned*)&h1);
        return;
    }
    if (bid < 4352) {                      // ---- rope table ----
        int i = (bid - 4096) * 256 + tid;  // TSEQ*32
        int tt = i >> 5, d2 = i & 31;
        float invf = exp2f(-(float)(2 * d2) * 0.20762050593046f);
        float s, c;
        sincosf((float)tt * invf, &s, &c);
        g_rope[i] = make_float2(c, s);
        return;
    }

    // ---- weight transpose+cast (64x64 tiles) ----
    const float* W;
    __half* Wt;
    int N, tix;
    if (bid < 5120) { tix = bid - 4352; W = W_qkv; Wt = g_wqkvT; N = 3 * DMODEL; }
    else            { tix = bid - 5120; W = W_out;  Wt = g_woutT; N = DMODEL; }
    const int nt = N / 64;
    const int n0 = (tix % nt) * 64, k0 = (tix / nt) * 64;

    #pragma unroll
    for (int p = 0; p < 4; p++) {
        int j = tid + p * 256;
        int k = j >> 4, c4 = j & 15;
        float4 v = *(const float4*)&W[(size_t)(k0 + k) * N + n0 + c4 * 4];
        tile[k][c4 * 4 + 0] = v.x;
        tile[k][c4 * 4 + 1] = v.y;
        tile[k][c4 * 4 + 2] = v.z;
        tile[k][c4 * 4 + 3] = v.w;
    }
    __syncthreads();
    #pragma unroll
    for (int p = 0; p < 2; p++) {
        int j = tid + p * 256;
        int n = j >> 3, kg = (j & 7) * 8;
        __half hv[8];
        #pragma unroll
        for (int i = 0; i < 8; i++)
            hv[i] = __float2half(tile[kg + i][n]);
        *(uint4*)&Wt[(size_t)(n0 + n) * DMODEL + k0 + kg] = *(uint4*)hv;
    }
}

// ---------------------------------------------------------------------------
// GEMM (round-9 config, UNCHANGED): 128x128 tile, BK=64, 3-stage cp.async,
// 8 warps (2x4), warp 64x32. mode 0: fp32 C + bias. mode 1: QKV epilogue.
// ---------------------------------------------------------------------------
__global__ __launch_bounds__(256)
void gemm_h_kernel(const __half* __restrict__ A, const __half* __restrict__ Bt,
                   const float* __restrict__ bias, float* __restrict__ C,
                   int M, int N, int mode)
{
    extern __shared__ __align__(16) char sm[];
    const int tid = threadIdx.x;
    const int wid = tid >> 5, lane = tid & 31;
    const int g = lane >> 2, t = lane & 3;
    const int bm = blockIdx.y * 128, bn = blockIdx.x * 128;
    const int wm = (wid & 1) * 64, wn = (wid >> 1) * 32;
    const unsigned sbase = smaddr(sm);

    const int lr = tid >> 1;                 // loader row 0..127
    const int lc = (tid & 1) * 4;            // 4 chunks each

    float acc[4][4][4];
    #pragma unroll
    for (int i = 0; i < 4; i++)
        #pragma unroll
        for (int j = 0; j < 4; j++)
            #pragma unroll
            for (int r = 0; r < 4; r++) acc[i][j][r] = 0.f;

    const __half* agp = &A[(size_t)(bm + lr) * 1024 + lc * 8];
    const __half* bgp = &Bt[(size_t)(bn + lr) * 1024 + lc * 8];

    // prologue: stages 0,1
    #pragma unroll
    for (int s = 0; s < 2; s++) {
        unsigned da = sbase + s * 16384, db = sbase + 49152 + s * 16384;
        #pragma unroll
        for (int c = 0; c < 4; c++) {
            cp16(da + swz(lr, lc + c), agp + s * 64 + c * 8);
            cp16(db + swz(lr, lc + c), bgp + s * 64 + c * 8);
        }
        cp_commit();
    }
    cp_wait1();
    __syncthreads();

    const unsigned arow = ((lane >> 3) & 1) * 8 + (lane & 7);
    const unsigned ach  = (lane >> 4);
    const unsigned brow = (lane >> 4) * 8 + (lane & 7);
    const unsigned bch  = (lane >> 3) & 1;

    int buf = 0, bufn = 2;
    #pragma unroll 1
    for (int s = 0; s < GEMM_KT; s++) {
        if (s + 2 < GEMM_KT) {
            unsigned da = sbase + bufn * 16384;
            unsigned db = sbase + 49152 + bufn * 16384;
            const __half* ag = agp + (s + 2) * 64;
            const __half* bg = bgp + (s + 2) * 64;
            #pragma unroll
            for (int c = 0; c < 4; c++) {
                cp16(da + swz(lr, lc + c), ag + c * 8);
                cp16(db + swz(lr, lc + c), bg + c * 8);
            }
            cp_commit();
        }

        const unsigned sa = sbase + buf * 16384;
        const unsigned sb = sbase + 49152 + buf * 16384;
        #pragma unroll
        for (int kk = 0; kk < 4; kk++) {
            unsigned af[4][4], bf[2][4];
            #pragma unroll
            for (int mt = 0; mt < 4; mt++)
                ldsm4(af[mt], sa + swz(wm + mt * 16 + arow, 2 * kk + ach));
            #pragma unroll
            for (int np = 0; np < 2; np++)
                ldsm4(bf[np], sb + swz(wn + np * 16 + brow, 2 * kk + bch));
            #pragma unroll
            for (int mt = 0; mt < 4; mt++)
                #pragma unroll
                for (int nt = 0; nt < 4; nt++)
                    mma_f16(acc[mt][nt], af[mt][0], af[mt][1], af[mt][2], af[mt][3],
                            bf[nt >> 1][(nt & 1) * 2], bf[nt >> 1][(nt & 1) * 2 + 1]);
        }

        if (s + 2 < GEMM_KT)      cp_wait1();
        else if (s + 1 < GEMM_KT) cp_wait0();
        if (s + 1 < GEMM_KT) __syncthreads();

        buf = (buf == 2) ? 0 : buf + 1;
        bufn = (bufn == 2) ? 0 : bufn + 1;
    }

    // ---------------- epilogue ----------------
    if (mode == 0) {
        #pragma unroll
        for (int mt = 0; mt < 4; mt++) {
            int row = bm + wm + mt * 16 + g;
            #pragma unroll
            for (int nt = 0; nt < 4; nt++) {
                int col = bn + wn + nt * 8 + 2 * t;
                float b0 = bias[col], b1 = bias[col + 1];
                *(float2*)&C[(size_t)row * N + col] =
                    make_float2(acc[mt][nt][0] + b0, acc[mt][nt][1] + b1);
                *(float2*)&C[(size_t)(row + 8) * N + col] =
                    make_float2(acc[mt][nt][2] + b0, acc[mt][nt][3] + b1);
            }
        }
    } else {
        #pragma unroll
        for (int nt = 0; nt < 4; nt++) {
            int col = bn + wn + nt * 8 + 2 * t;
            int qi = col >> 10, rem = col & 1023;
            int h = rem >> 6, d0 = rem & 63;
            __half* dst = (qi == 0) ? g_qh : (qi == 1) ? g_kh : g_vh;
            float b0 = bias[col], b1 = bias[col + 1];
            #pragma unroll
            for (int mt = 0; mt < 4; mt++) {
                int row = bm + wm + mt * 16 + g;
                #pragma unroll
                for (int half = 0; half < 2; half++) {
                    int r = row + half * 8;
                    float x1 = acc[mt][nt][half * 2]     + b0;
                    float x2 = acc[mt][nt][half * 2 + 1] + b1;
                    int bb = r >> 11, tr = r & 2047;
                    size_t o = ((size_t)(bb * NH + h) * TSEQ + tr) * DK + d0;
                    if (qi < 2) {
                        float2 cs = g_rope[tr * 32 + (d0 >> 1)];
                        *(__half2*)&dst[o] = __floats2half2_rn(
                            x1 * cs.x - x2 * cs.y, x1 * cs.y + x2 * cs.x);
                    } else {
                        *(__half2*)&dst[o] = __floats2half2_rn(x1, x2);
                    }
                }
            }
        }
    }
}

// ---------------------------------------------------------------------------
// Flash attention: fp16-ACCUMULATOR mma for S and per-tile PV (K=64 sums),
// fp32 running state. cp.async double buffer, exp2 softmax, masked-tile skip.
// ---------------------------------------------------------------------------
#define SCL2E 0.18033688011112042f   // (1/8) * log2(e)

__global__ __launch_bounds__(256)
void flash_h_kernel()
{
    extern __shared__ __align__(16) char sm[];
    char* Qs = sm;                               // 16KB (128x64)
    char* Ks[2] = { sm + 16384, sm + 24576 };    // 8KB each (64x64)
    char* Vs[2] = { sm + 32768, sm + 40960 };

    const int tid = threadIdx.x;
    const int wid = tid >> 5, lane = tid & 31;
    const int g = lane >> 2, t = lane & 3;
    const int qx = (TSEQ / 128 - 1) - (blockIdx.x >> 5);  // big tiles first
    const int bh = blockIdx.x & 31;
    const int b = bh >> 4, h = bh & 15;
    const int qb = qx * 128;

    const __half* Qp = g_qh + (size_t)bh * TSEQ * DK;
    const __half* Kp = g_kh + (size_t)bh * TSEQ * DK;
    const __half* Vp = g_vh + (size_t)bh * TSEQ * DK;

    const int lr  = tid >> 1;
    const int lc  = (tid & 1) * 4;
    const int kvr = tid >> 2;
    const int kvc = (tid & 3) * 2;

    {
        unsigned sq = smaddr(Qs);
        #pragma unroll
        for (int c = 0; c < 4; c++)
            cp16(sq + swz(lr, lc + c), &Qp[(size_t)(qb + lr) * DK + (lc + c) * 8]);
        cp_commit();
        unsigned sk = smaddr(Ks[0]), sv = smaddr(Vs[0]);
        #pragma unroll
        for (int c = 0; c < 2; c++) {
            cp16(sk + swz(kvr, kvc + c), &Kp[(size_t)kvr * DK + (kvc + c) * 8]);
            cp16(sv + swz(kvr, kvc + c), &Vp[(size_t)kvr * DK + (kvc + c) * 8]);
        }
        cp_commit();
    }

    unsigned qa[4][4];
    float o[8][4];
    #pragma unroll
    for (int nt = 0; nt < 8; nt++)
        #pragma unroll
        for (int r = 0; r < 4; r++) o[nt][r] = 0.f;
    float m0 = -INFINITY, m1 = -INFINITY, l0 = 0.f, l1 = 0.f;
    const int tiles = 2 * qx + 2;

    const unsigned arow = ((lane >> 3) & 1) * 8 + (lane & 7);
    const unsigned ach  = (lane >> 4);
    const unsigned brow = (lane >> 4) * 8 + (lane & 7);
    const unsigned bch  = (lane >> 3) & 1;

    for (int j = 0; j < tiles; j++) {
        __syncthreads();
        if (j + 1 < tiles) {
            int st = (j + 1) & 1, s0 = (j + 1) * 64;
            unsigned sk = smaddr(Ks[st]), sv = smaddr(Vs[st]);
            #pragma unroll
            for (int c = 0; c < 2; c++) {
                cp16(sk + swz(kvr, kvc + c), &Kp[(size_t)(s0 + kvr) * DK + (kvc + c) * 8]);
                cp16(sv + swz(kvr, kvc + c), &Vp[(size_t)(s0 + kvr) * DK + (kvc + c) * 8]);
            }
            cp_commit();
            cp_wait1();
        } else {
            cp_wait0();
        }
        __syncthreads();

        if (j == 0) {
            unsigned sq = smaddr(Qs);
            #pragma unroll
            for (int kk = 0; kk < 4; kk++)
                ldsm4(qa[kk], sq + swz(wid * 16 + arow, 2 * kk + ach));
        }

        // Fully-masked tile for upper warps: P == 0, state provably unchanged.
        if (j == 2 * qx + 1 && wid < 4) continue;

        const unsigned sk = smaddr(Ks[j & 1]), sv = smaddr(Vs[j & 1]);

        // S = Q K^T with fp16 accumulator (K=64 sums)
        unsigned sh[8][2];
        #pragma unroll
        for (int nt = 0; nt < 8; nt++) { sh[nt][0] = 0u; sh[nt][1] = 0u; }
        #pragma unroll
        for (int kk = 0; kk < 4; kk++) {
            unsigned kf[4][4];
            #pragma unroll
            for (int np = 0; np < 4; np++)
                ldsm4(kf[np], sk + swz(np * 16 + brow, 2 * kk + bch));
            #pragma unroll
            for (int nt = 0; nt < 8; nt++)
                mma_h16(sh[nt], qa[kk][0], qa[kk][1], qa[kk][2], qa[kk][3],
                        kf[nt >> 1][(nt & 1) * 2], kf[nt >> 1][(nt & 1) * 2 + 1]);
        }
        // unpack to fp32 for softmax
        float sa[8][4];
        #pragma unroll
        for (int nt = 0; nt < 8; nt++) {
            float2 lo = __half22float2(*(__half2*)&sh[nt][0]);
            float2 hi = __half22float2(*(__half2*)&sh[nt][1]);
            sa[nt][0] = lo.x; sa[nt][1] = lo.y;
            sa[nt][2] = hi.x; sa[nt][3] = hi.y;
        }

        // mask only where the warp strip straddles the diagonal
        if ((j == 2 * qx && wid < 4) || (j == 2 * qx + 1 && wid >= 4)) {
            int row0 = qb + wid * 16 + g, row1 = row0 + 8;
            #pragma unroll
            for (int nt = 0; nt < 8; nt++) {
                int c = j * 64 + nt * 8 + 2 * t;
                if (c > row0)     sa[nt][0] = -1e30f;
                if (c + 1 > row0) sa[nt][1] = -1e30f;
                if (c > row1)     sa[nt][2] = -1e30f;
                if (c + 1 > row1) sa[nt][3] = -1e30f;
            }
        }

        float rm0 = -INFINITY, rm1 = -INFINITY;
        #pragma unroll
        for (int nt = 0; nt < 8; nt++) {
            rm0 = fmaxf(rm0, fmaxf(sa[nt][0], sa[nt][1]));
            rm1 = fmaxf(rm1, fmaxf(sa[nt][2], sa[nt][3]));
        }
        rm0 = fmaxf(rm0, __shfl_xor_sync(0xffffffffu, rm0, 1));
        rm0 = fmaxf(rm0, __shfl_xor_sync(0xffffffffu, rm0, 2));
        rm1 = fmaxf(rm1, __shfl_xor_sync(0xffffffffu, rm1, 1));
        rm1 = fmaxf(rm1, __shfl_xor_sync(0xffffffffu, rm1, 2));

        float M0 = fmaxf(m0, rm0), M1 = fmaxf(m1, rm1);
        float a0 = exp2f((m0 - M0) * SCL2E);
        float a1 = exp2f((m1 - M1) * SCL2E);
        float M0s = M0 * SCL2E, M1s = M1 * SCL2E;

        unsigned pa[8], pb[8];
        float rs0 = 0.f, rs1 = 0.f;
        #pragma unroll
        for (int nt = 0; nt < 8; nt++) {
            float p00 = exp2f(fmaf(sa[nt][0], SCL2E, -M0s));
            float p01 = exp2f(fmaf(sa[nt][1], SCL2E, -M0s));
            float p10 = exp2f(fmaf(sa[nt][2], SCL2E, -M1s));
            float p11 = exp2f(fmaf(sa[nt][3], SCL2E, -M1s));
            rs0 += p00 + p01;
            rs1 += p10 + p11;
            pa[nt] = pack_h2(p00, p01);
            pb[nt] = pack_h2(p10, p11);
        }
        rs0 += __shfl_xor_sync(0xffffffffu, rs0, 1);
        rs0 += __shfl_xor_sync(0xffffffffu, rs0, 2);
        rs1 += __shfl_xor_sync(0xffffffffu, rs1, 1);
        rs1 += __shfl_xor_sync(0xffffffffu, rs1, 2);
        l0 = l0 * a0 + rs0;
        l1 = l1 * a1 + rs1;
        m0 = M0; m1 = M1;

        // PV with per-tile fp16 accumulator, promoted into fp32 running O
        unsigned oh[8][2];
        #pragma unroll
        for (int nt = 0; nt < 8; nt++) { oh[nt][0] = 0u; oh[nt][1] = 0u; }
        #pragma unroll
        for (int kk = 0; kk < 4; kk++) {
            unsigned vf[4][4];
            #pragma unroll
            for (int np = 0; np < 4; np++)
                ldsm4t(vf[np], sv + swz(16 * kk + arow, np * 2 + ach));
            unsigned A0 = pa[2 * kk], A1 = pb[2 * kk];
            unsigned A2 = pa[2 * kk + 1], A3 = pb[2 * kk + 1];
            #pragma unroll
            for (int nt = 0; nt < 8; nt++)
                mma_h16(oh[nt], A0, A1, A2, A3,
                        vf[nt >> 1][(nt & 1) * 2], vf[nt >> 1][(nt & 1) * 2 + 1]);
        }
        #pragma unroll
        for (int nt = 0; nt < 8; nt++) {
            float2 lo = __half22float2(*(__half2*)&oh[nt][0]);
            float2 hi = __half22float2(*(__half2*)&oh[nt][1]);
            o[nt][0] = fmaf(o[nt][0], a0, lo.x);
            o[nt][1] = fmaf(o[nt][1], a0, lo.y);
            o[nt][2] = fmaf(o[nt][2], a1, hi.x);
            o[nt][3] = fmaf(o[nt][3], a1, hi.y);
        }
    }

    float i0 = 1.f / l0, i1 = 1.f / l1;
    int row0 = qb + wid * 16 + g;
    size_t gr0 = (size_t)(b * TSEQ + row0) * DMODEL;
    size_t gr1 = (size_t)(b * TSEQ + row0 + 8) * DMODEL;
    #pragma unroll
    for (int nt = 0; nt < 8; nt++) {
        int col = h * DK + nt * 8 + 2 * t;
        *(__half2*)&g_attn[gr0 + col] = __floats2half2_rn(o[nt][0] * i0, o[nt][1] * i0);
        *(__half2*)&g_attn[gr1 + col] = __floats2half2_rn(o[nt][2] * i1, o[nt][3] * i1);
    }
}

// ---------------------------------------------------------------------------
extern "C" void kernel_launch(void* const* d_in, const int* in_sizes, int n_in,
                              void* d_out, int out_size)
{
    const float* x     = (const float*)d_in[0];
    const float* W_qkv = (const float*)d_in[1];
    const float* b_qkv = (const float*)d_in[2];
    const float* W_out = (const float*)d_in[3];
    const float* b_out = (const float*)d_in[4];
    float* out = (float*)d_out;

    __half* xh;     cudaGetSymbolAddress((void**)&xh,     g_xh);
    __half* wqkvT;  cudaGetSymbolAddress((void**)&wqkvT,  g_wqkvT);
    __half* woutT;  cudaGetSymbolAddress((void**)&woutT,  g_woutT);
    __half* attn;   cudaGetSymbolAddress((void**)&attn,   g_attn);

    const int gemm_smem = 98304;   // 3 x (16K A + 16K B)
    cudaFuncSetAttribute(gemm_h_kernel,
                         cudaFuncAttributeMaxDynamicSharedMemorySize, gemm_smem);
    cudaFuncSetAttribute(flash_h_kernel,
                         cudaFuncAttributeMaxDynamicSharedMemorySize, 49152);

    // 0) fused prep (cast x, rope table, both weight transposes)
    prep_kernel<<<5376, 256>>>(x, W_qkv, W_out);

    // 1) QKV projection + fused bias/RoPE/split (mode 1)
    {
        dim3 grid(3 * DMODEL / 128, BT / 128);
        gemm_h_kernel<<<grid, 256, gemm_smem>>>(xh, wqkvT, b_qkv, nullptr,
                                                BT, 3 * DMODEL, 1);
    }

    // 2) flash attention (global big-first ordering)
    flash_h_kernel<<<(TSEQ / 128) * BSZ * NH, 256, 49152>>>();

    // 3) output projection (mode 0) -> d_out
    {
        dim3 grid(DMODEL / 128, BT / 128);
        gemm_h_kernel<<<grid, 256, gemm_smem>>>(attn, woutT, b_out, out,
                                                BT, DMODEL, 0);
    }
}

// round 14
// speedup vs baseline: 1.5522x; 1.5522x over previous
#include <cuda_runtime.h>
#include <cuda_fp16.h>
#include <math.h>

#define BSZ 2
#define TSEQ 2048
#define DMODEL 1024
#define NH 16
#define DK 64
#define BT (BSZ * TSEQ)          // 4096
#define GEMM_KT 16               // K=1024 / BK=64

// ---------------- scratch ----------------
__device__ __half g_xh[BT * DMODEL];
__device__ __half g_wqkvT[3 * DMODEL * DMODEL];           // [3072][1024]
__device__ __half g_woutT[DMODEL * DMODEL];               // [1024][1024]
__device__ __half g_qh[BSZ * NH * TSEQ * DK];             // [bh][t][d]
__device__ __half g_kh[BSZ * NH * TSEQ * DK];
__device__ __half g_vh[BSZ * NH * TSEQ * DK];
__device__ __half g_attn[BT * DMODEL];
__device__ float2 g_rope[TSEQ * 32];                      // (cos,sin) per (t, d2)

// swizzle: 64-half rows (128B), 16B chunks
__device__ __forceinline__ unsigned swz(unsigned row, unsigned chunk) {
    return row * 128u + ((chunk ^ (row & 7u)) << 4);
}
__device__ __forceinline__ unsigned smaddr(const void* p) {
    return (unsigned)__cvta_generic_to_shared(p);
}
__device__ __forceinline__ void cp16(unsigned s, const void* g) {
    asm volatile("cp.async.cg.shared.global [%0], [%1], 16;\n" :: "r"(s), "l"(g));
}
__device__ __forceinline__ void cp_commit() { asm volatile("cp.async.commit_group;\n" ::); }
__device__ __forceinline__ void cp_wait0() { asm volatile("cp.async.wait_group 0;\n" ::); }
__device__ __forceinline__ void cp_wait1() { asm volatile("cp.async.wait_group 1;\n" ::); }
__device__ __forceinline__ void cp_wait2() { asm volatile("cp.async.wait_group 2;\n" ::); }

__device__ __forceinline__ void ldsm4(unsigned* r, unsigned a) {
    asm volatile("ldmatrix.sync.aligned.m8n8.x4.shared.b16 {%0,%1,%2,%3}, [%4];\n"
                 : "=r"(r[0]), "=r"(r[1]), "=r"(r[2]), "=r"(r[3]) : "r"(a));
}
__device__ __forceinline__ void ldsm4t(unsigned* r, unsigned a) {
    asm volatile("ldmatrix.sync.aligned.m8n8.x4.trans.shared.b16 {%0,%1,%2,%3}, [%4];\n"
                 : "=r"(r[0]), "=r"(r[1]), "=r"(r[2]), "=r"(r[3]) : "r"(a));
}
__device__ __forceinline__ void mma_f16(float* c, unsigned a0, unsigned a1,
                                        unsigned a2, unsigned a3,
                                        unsigned b0, unsigned b1) {
    asm volatile(
        "mma.sync.aligned.m16n8k16.row.col.f32.f16.f16.f32 "
        "{%0,%1,%2,%3}, {%4,%5,%6,%7}, {%8,%9}, {%0,%1,%2,%3};\n"
        : "+f"(c[0]), "+f"(c[1]), "+f"(c[2]), "+f"(c[3])
        : "r"(a0), "r"(a1), "r"(a2), "r"(a3), "r"(b0), "r"(b1));
}
__device__ __forceinline__ unsigned pack_h2(float a, float b) {
    __half2 h = __floats2half2_rn(a, b);
    return *reinterpret_cast<unsigned*>(&h);
}

// ---------------------------------------------------------------------------
// Fused prep: one launch does cast_x + rope table + both weight transposes.
// ---------------------------------------------------------------------------
__global__ __launch_bounds__(256)
void prep_kernel(const float* __restrict__ x,
                 const float* __restrict__ W_qkv,
                 const float* __restrict__ W_out)
{
    __shared__ float tile[64][65];
    const int bid = blockIdx.x;
    const int tid = threadIdx.x;

    if (bid < 4096) {                      // ---- cast x ----
        int i = bid * 256 + tid;           // float4 index
        float4 v = ((const float4*)x)[i];
        __half2 h0 = __floats2half2_rn(v.x, v.y);
        __half2 h1 = __floats2half2_rn(v.z, v.w);
        ((uint2*)g_xh)[i] = make_uint2(*(unsigned*)&h0, *(unsigned*)&h1);
        return;
    }
    if (bid < 4352) {                      // ---- rope table ----
        int i = (bid - 4096) * 256 + tid;  // TSEQ*32
        int tt = i >> 5, d2 = i & 31;
        float invf = exp2f(-(float)(2 * d2) * 0.20762050593046f);
        float s, c;
        sincosf((float)tt * invf, &s, &c);
        g_rope[i] = make_float2(c, s);
        return;
    }

    // ---- weight transpose+cast (64x64 tiles) ----
    const float* W;
    __half* Wt;
    int N, tix;
    if (bid < 5120) { tix = bid - 4352; W = W_qkv; Wt = g_wqkvT; N = 3 * DMODEL; }
    else            { tix = bid - 5120; W = W_out;  Wt = g_woutT; N = DMODEL; }
    const int nt = N / 64;
    const int n0 = (tix % nt) * 64, k0 = (tix / nt) * 64;

    #pragma unroll
    for (int p = 0; p < 4; p++) {
        int j = tid + p * 256;
        int k = j >> 4, c4 = j & 15;
        float4 v = *(const float4*)&W[(size_t)(k0 + k) * N + n0 + c4 * 4];
        tile[k][c4 * 4 + 0] = v.x;
        tile[k][c4 * 4 + 1] = v.y;
        tile[k][c4 * 4 + 2] = v.z;
        tile[k][c4 * 4 + 3] = v.w;
    }
    __syncthreads();
    #pragma unroll
    for (int p = 0; p < 2; p++) {
        int j = tid + p * 256;
        int n = j >> 3, kg = (j & 7) * 8;
        __half hv[8];
        #pragma unroll
        for (int i = 0; i < 8; i++)
            hv[i] = __float2half(tile[kg + i][n]);
        *(uint4*)&Wt[(size_t)(n0 + n) * DMODEL + k0 + kg] = *(uint4*)hv;
    }
}

// ---------------------------------------------------------------------------
// GEMM (round-9 config, UNCHANGED): 128x128 tile, BK=64, 3-stage cp.async,
// 8 warps (2x4), warp 64x32. mode 0: fp32 C + bias. mode 1: QKV epilogue.
// ---------------------------------------------------------------------------
__global__ __launch_bounds__(256)
void gemm_h_kernel(const __half* __restrict__ A, const __half* __restrict__ Bt,
                   const float* __restrict__ bias, float* __restrict__ C,
                   int M, int N, int mode)
{
    extern __shared__ __align__(16) char sm[];
    const int tid = threadIdx.x;
    const int wid = tid >> 5, lane = tid & 31;
    const int g = lane >> 2, t = lane & 3;
    const int bm = blockIdx.y * 128, bn = blockIdx.x * 128;
    const int wm = (wid & 1) * 64, wn = (wid >> 1) * 32;
    const unsigned sbase = smaddr(sm);

    const int lr = tid >> 1;                 // loader row 0..127
    const int lc = (tid & 1) * 4;            // 4 chunks each

    float acc[4][4][4];
    #pragma unroll
    for (int i = 0; i < 4; i++)
        #pragma unroll
        for (int j = 0; j < 4; j++)
            #pragma unroll
            for (int r = 0; r < 4; r++) acc[i][j][r] = 0.f;

    const __half* agp = &A[(size_t)(bm + lr) * 1024 + lc * 8];
    const __half* bgp = &Bt[(size_t)(bn + lr) * 1024 + lc * 8];

    // prologue: stages 0,1
    #pragma unroll
    for (int s = 0; s < 2; s++) {
        unsigned da = sbase + s * 16384, db = sbase + 49152 + s * 16384;
        #pragma unroll
        for (int c = 0; c < 4; c++) {
            cp16(da + swz(lr, lc + c), agp + s * 64 + c * 8);
            cp16(db + swz(lr, lc + c), bgp + s * 64 + c * 8);
        }
        cp_commit();
    }
    cp_wait1();
    __syncthreads();

    const unsigned arow = ((lane >> 3) & 1) * 8 + (lane & 7);
    const unsigned ach  = (lane >> 4);
    const unsigned brow = (lane >> 4) * 8 + (lane & 7);
    const unsigned bch  = (lane >> 3) & 1;

    int buf = 0, bufn = 2;
    #pragma unroll 1
    for (int s = 0; s < GEMM_KT; s++) {
        if (s + 2 < GEMM_KT) {
            unsigned da = sbase + bufn * 16384;
            unsigned db = sbase + 49152 + bufn * 16384;
            const __half* ag = agp + (s + 2) * 64;
            const __half* bg = bgp + (s + 2) * 64;
            #pragma unroll
            for (int c = 0; c < 4; c++) {
                cp16(da + swz(lr, lc + c), ag + c * 8);
                cp16(db + swz(lr, lc + c), bg + c * 8);
            }
            cp_commit();
        }

        const unsigned sa = sbase + buf * 16384;
        const unsigned sb = sbase + 49152 + buf * 16384;
        #pragma unroll
        for (int kk = 0; kk < 4; kk++) {
            unsigned af[4][4], bf[2][4];
            #pragma unroll
            for (int mt = 0; mt < 4; mt++)
                ldsm4(af[mt], sa + swz(wm + mt * 16 + arow, 2 * kk + ach));
            #pragma unroll
            for (int np = 0; np < 2; np++)
                ldsm4(bf[np], sb + swz(wn + np * 16 + brow, 2 * kk + bch));
            #pragma unroll
            for (int mt = 0; mt < 4; mt++)
                #pragma unroll
                for (int nt = 0; nt < 4; nt++)
                    mma_f16(acc[mt][nt], af[mt][0], af[mt][1], af[mt][2], af[mt][3],
                            bf[nt >> 1][(nt & 1) * 2], bf[nt >> 1][(nt & 1) * 2 + 1]);
        }

        if (s + 2 < GEMM_KT)      cp_wait1();
        else if (s + 1 < GEMM_KT) cp_wait0();
        if (s + 1 < GEMM_KT) __syncthreads();

        buf = (buf == 2) ? 0 : buf + 1;
        bufn = (bufn == 2) ? 0 : bufn + 1;
    }

    // ---------------- epilogue ----------------
    if (mode == 0) {
        #pragma unroll
        for (int mt = 0; mt < 4; mt++) {
            int row = bm + wm + mt * 16 + g;
            #pragma unroll
            for (int nt = 0; nt < 4; nt++) {
                int col = bn + wn + nt * 8 + 2 * t;
                float b0 = bias[col], b1 = bias[col + 1];
                *(float2*)&C[(size_t)row * N + col] =
                    make_float2(acc[mt][nt][0] + b0, acc[mt][nt][1] + b1);
                *(float2*)&C[(size_t)(row + 8) * N + col] =
                    make_float2(acc[mt][nt][2] + b0, acc[mt][nt][3] + b1);
            }
        }
    } else {
        #pragma unroll
        for (int nt = 0; nt < 4; nt++) {
            int col = bn + wn + nt * 8 + 2 * t;
            int qi = col >> 10, rem = col & 1023;
            int h = rem >> 6, d0 = rem & 63;
            __half* dst = (qi == 0) ? g_qh : (qi == 1) ? g_kh : g_vh;
            float b0 = bias[col], b1 = bias[col + 1];
            #pragma unroll
            for (int mt = 0; mt < 4; mt++) {
                int row = bm + wm + mt * 16 + g;
                #pragma unroll
                for (int half = 0; half < 2; half++) {
                    int r = row + half * 8;
                    float x1 = acc[mt][nt][half * 2]     + b0;
                    float x2 = acc[mt][nt][half * 2 + 1] + b1;
                    int bb = r >> 11, tr = r & 2047;
                    size_t o = ((size_t)(bb * NH + h) * TSEQ + tr) * DK + d0;
                    if (qi < 2) {
                        float2 cs = g_rope[tr * 32 + (d0 >> 1)];
                        *(__half2*)&dst[o] = __floats2half2_rn(
                            x1 * cs.x - x2 * cs.y, x1 * cs.y + x2 * cs.x);
                    } else {
                        *(__half2*)&dst[o] = __floats2half2_rn(x1, x2);
                    }
                }
            }
        }
    }
}

// ---------------------------------------------------------------------------
// Flash attention (round-12 numerics, fp32 acc): 3-stage K/V cp.async
// pipeline (2 tiles in flight), exp2 softmax, masked-tile skip.
// ---------------------------------------------------------------------------
#define SCL2E 0.18033688011112042f   // (1/8) * log2(e)

__global__ __launch_bounds__(256)
void flash_h_kernel()
{
    extern __shared__ __align__(16) char sm[];
    char* Qs = sm;                                           // 16KB (128x64)
    char* Ks[3] = { sm + 16384, sm + 24576, sm + 32768 };    // 8KB each
    char* Vs[3] = { sm + 40960, sm + 49152, sm + 57344 };

    const int tid = threadIdx.x;
    const int wid = tid >> 5, lane = tid & 31;
    const int g = lane >> 2, t = lane & 3;
    const int qx = (TSEQ / 128 - 1) - (blockIdx.x >> 5);  // big tiles first
    const int bh = blockIdx.x & 31;
    const int b = bh >> 4, h = bh & 15;
    const int qb = qx * 128;

    const __half* Qp = g_qh + (size_t)bh * TSEQ * DK;
    const __half* Kp = g_kh + (size_t)bh * TSEQ * DK;
    const __half* Vp = g_vh + (size_t)bh * TSEQ * DK;

    const int lr  = tid >> 1;
    const int lc  = (tid & 1) * 4;
    const int kvr = tid >> 2;
    const int kvc = (tid & 3) * 2;

    const int tiles = 2 * qx + 2;   // >= 2 always

    // prologue: Q group, then KV tiles 0 and 1
    {
        unsigned sq = smaddr(Qs);
        #pragma unroll
        for (int c = 0; c < 4; c++)
            cp16(sq + swz(lr, lc + c), &Qp[(size_t)(qb + lr) * DK + (lc + c) * 8]);
        cp_commit();
        #pragma unroll
        for (int s = 0; s < 2; s++) {
            unsigned sk = smaddr(Ks[s]), sv = smaddr(Vs[s]);
            #pragma unroll
            for (int c = 0; c < 2; c++) {
                cp16(sk + swz(kvr, kvc + c), &Kp[(size_t)(s * 64 + kvr) * DK + (kvc + c) * 8]);
                cp16(sv + swz(kvr, kvc + c), &Vp[(size_t)(s * 64 + kvr) * DK + (kvc + c) * 8]);
            }
            cp_commit();
        }
    }

    unsigned qa[4][4];
    float o[8][4];
    #pragma unroll
    for (int nt = 0; nt < 8; nt++)
        #pragma unroll
        for (int r = 0; r < 4; r++) o[nt][r] = 0.f;
    float m0 = -INFINITY, m1 = -INFINITY, l0 = 0.f, l1 = 0.f;

    const unsigned arow = ((lane >> 3) & 1) * 8 + (lane & 7);
    const unsigned ach  = (lane >> 4);
    const unsigned brow = (lane >> 4) * 8 + (lane & 7);
    const unsigned bch  = (lane >> 3) & 1;

    int buf = 0;                 // j % 3
    for (int j = 0; j < tiles; j++) {
        __syncthreads();         // readers of buffer (j+2)%3 (tile j-1) done
        if (j + 2 < tiles) {
            int st = (j + 2) % 3, s0 = (j + 2) * 64;
            unsigned sk = smaddr(Ks[st]), sv = smaddr(Vs[st]);
            #pragma unroll
            for (int c = 0; c < 2; c++) {
                cp16(sk + swz(kvr, kvc + c), &Kp[(size_t)(s0 + kvr) * DK + (kvc + c) * 8]);
                cp16(sv + swz(kvr, kvc + c), &Vp[(size_t)(s0 + kvr) * DK + (kvc + c) * 8]);
            }
            cp_commit();
            cp_wait2();          // tile j ready; tiles j+1, j+2 may be pending
        } else if (j + 1 < tiles) {
            cp_wait1();
        } else {
            cp_wait0();
        }
        __syncthreads();

        if (j == 0) {
            unsigned sq = smaddr(Qs);
            #pragma unroll
            for (int kk = 0; kk < 4; kk++)
                ldsm4(qa[kk], sq + swz(wid * 16 + arow, 2 * kk + ach));
        }

        // Fully-masked tile for upper warps: P == 0, state provably unchanged.
        if (j == 2 * qx + 1 && wid < 4) { buf = (buf == 2) ? 0 : buf + 1; continue; }

        const unsigned sk = smaddr(Ks[buf]), sv = smaddr(Vs[buf]);

        float sa[8][4];
        #pragma unroll
        for (int nt = 0; nt < 8; nt++)
            #pragma unroll
            for (int r = 0; r < 4; r++) sa[nt][r] = 0.f;
        #pragma unroll
        for (int kk = 0; kk < 4; kk++) {
            unsigned kf[4][4];
            #pragma unroll
            for (int np = 0; np < 4; np++)
                ldsm4(kf[np], sk + swz(np * 16 + brow, 2 * kk + bch));
            #pragma unroll
            for (int nt = 0; nt < 8; nt++)
                mma_f16(sa[nt], qa[kk][0], qa[kk][1], qa[kk][2], qa[kk][3],
                        kf[nt >> 1][(nt & 1) * 2], kf[nt >> 1][(nt & 1) * 2 + 1]);
        }

        // mask only where the warp strip straddles the diagonal
        if ((j == 2 * qx && wid < 4) || (j == 2 * qx + 1 && wid >= 4)) {
            int row0 = qb + wid * 16 + g, row1 = row0 + 8;
            #pragma unroll
            for (int nt = 0; nt < 8; nt++) {
                int c = j * 64 + nt * 8 + 2 * t;
                if (c > row0)     sa[nt][0] = -1e30f;
                if (c + 1 > row0) sa[nt][1] = -1e30f;
                if (c > row1)     sa[nt][2] = -1e30f;
                if (c + 1 > row1) sa[nt][3] = -1e30f;
            }
        }

        float rm0 = -INFINITY, rm1 = -INFINITY;
        #pragma unroll
        for (int nt = 0; nt < 8; nt++) {
            rm0 = fmaxf(rm0, fmaxf(sa[nt][0], sa[nt][1]));
            rm1 = fmaxf(rm1, fmaxf(sa[nt][2], sa[nt][3]));
        }
        rm0 = fmaxf(rm0, __shfl_xor_sync(0xffffffffu, rm0, 1));
        rm0 = fmaxf(rm0, __shfl_xor_sync(0xffffffffu, rm0, 2));
        rm1 = fmaxf(rm1, __shfl_xor_sync(0xffffffffu, rm1, 1));
        rm1 = fmaxf(rm1, __shfl_xor_sync(0xffffffffu, rm1, 2));

        float M0 = fmaxf(m0, rm0), M1 = fmaxf(m1, rm1);
        float a0 = exp2f((m0 - M0) * SCL2E);
        float a1 = exp2f((m1 - M1) * SCL2E);
        float M0s = M0 * SCL2E, M1s = M1 * SCL2E;

        unsigned pa[8], pb[8];
        float rs0 = 0.f, rs1 = 0.f;
        #pragma unroll
        for (int nt = 0; nt < 8; nt++) {
            float p00 = exp2f(fmaf(sa[nt][0], SCL2E, -M0s));
            float p01 = exp2f(fmaf(sa[nt][1], SCL2E, -M0s));
            float p10 = exp2f(fmaf(sa[nt][2], SCL2E, -M1s));
            float p11 = exp2f(fmaf(sa[nt][3], SCL2E, -M1s));
            rs0 += p00 + p01;
            rs1 += p10 + p11;
            pa[nt] = pack_h2(p00, p01);
            pb[nt] = pack_h2(p10, p11);
        }
        rs0 += __shfl_xor_sync(0xffffffffu, rs0, 1);
        rs0 += __shfl_xor_sync(0xffffffffu, rs0, 2);
        rs1 += __shfl_xor_sync(0xffffffffu, rs1, 1);
        rs1 += __shfl_xor_sync(0xffffffffu, rs1, 2);
        l0 = l0 * a0 + rs0;
        l1 = l1 * a1 + rs1;
        m0 = M0; m1 = M1;

        #pragma unroll
        for (int nt = 0; nt < 8; nt++) {
            o[nt][0] *= a0; o[nt][1] *= a0;
            o[nt][2] *= a1; o[nt][3] *= a1;
        }

        #pragma unroll
        for (int kk = 0; kk < 4; kk++) {
            unsigned vf[4][4];
            #pragma unroll
            for (int np = 0; np < 4; np++)
                ldsm4t(vf[np], sv + swz(16 * kk + arow, np * 2 + ach));
            unsigned A0 = pa[2 * kk], A1 = pb[2 * kk];
            unsigned A2 = pa[2 * kk + 1], A3 = pb[2 * kk + 1];
            #pragma unroll
            for (int nt = 0; nt < 8; nt++)
                mma_f16(o[nt], A0, A1, A2, A3,
                        vf[nt >> 1][(nt & 1) * 2], vf[nt >> 1][(nt & 1) * 2 + 1]);
        }

        buf = (buf == 2) ? 0 : buf + 1;
    }

    float i0 = 1.f / l0, i1 = 1.f / l1;
    int row0 = qb + wid * 16 + g;
    size_t gr0 = (size_t)(b * TSEQ + row0) * DMODEL;
    size_t gr1 = (size_t)(b * TSEQ + row0 + 8) * DMODEL;
    #pragma unroll
    for (int nt = 0; nt < 8; nt++) {
        int col = h * DK + nt * 8 + 2 * t;
        *(__half2*)&g_attn[gr0 + col] = __floats2half2_rn(o[nt][0] * i0, o[nt][1] * i0);
        *(__half2*)&g_attn[gr1 + col] = __floats2half2_rn(o[nt][2] * i1, o[nt][3] * i1);
    }
}

// ---------------------------------------------------------------------------
extern "C" void kernel_launch(void* const* d_in, const int* in_sizes, int n_in,
                              void* d_out, int out_size)
{
    const float* x     = (const float*)d_in[0];
    const float* W_qkv = (const float*)d_in[1];
    const float* b_qkv = (const float*)d_in[2];
    const float* W_out = (const float*)d_in[3];
    const float* b_out = (const float*)d_in[4];
    float* out = (float*)d_out;

    __half* xh;     cudaGetSymbolAddress((void**)&xh,     g_xh);
    __half* wqkvT;  cudaGetSymbolAddress((void**)&wqkvT,  g_wqkvT);
    __half* woutT;  cudaGetSymbolAddress((void**)&woutT,  g_woutT);
    __half* attn;   cudaGetSymbolAddress((void**)&attn,   g_attn);

    const int gemm_smem = 98304;   // 3 x (16K A + 16K B)
    cudaFuncSetAttribute(gemm_h_kernel,
                         cudaFuncAttributeMaxDynamicSharedMemorySize, gemm_smem);
    cudaFuncSetAttribute(flash_h_kernel,
                         cudaFuncAttributeMaxDynamicSharedMemorySize, 65536);

    // 0) fused prep (cast x, rope table, both weight transposes)
    prep_kernel<<<5376, 256>>>(x, W_qkv, W_out);

    // 1) QKV projection + fused bias/RoPE/split (mode 1)
    {
        dim3 grid(3 * DMODEL / 128, BT / 128);
        gemm_h_kernel<<<grid, 256, gemm_smem>>>(xh, wqkvT, b_qkv, nullptr,
                                                BT, 3 * DMODEL, 1);
    }

    // 2) flash attention (global big-first ordering)
    flash_h_kernel<<<(TSEQ / 128) * BSZ * NH, 256, 65536>>>();

    // 3) output projection (mode 0) -> d_out
    {
        dim3 grid(DMODEL / 128, BT / 128);
        gemm_h_kernel<<<grid, 256, gemm_smem>>>(attn, woutT, b_out, out,
                                                BT, DMODEL, 0);
    }
}

// round 15
// speedup vs baseline: 1.7446x; 1.1239x over previous
#include <cuda_runtime.h>
#include <cuda_fp16.h>
#include <math.h>

#define BSZ 2
#define TSEQ 2048
#define DMODEL 1024
#define NH 16
#define DK 64
#define BT (BSZ * TSEQ)          // 4096
#define GEMM_KT 16               // K=1024 / BK=64

// ---------------- scratch ----------------
__device__ __half g_xh[BT * DMODEL];
__device__ __half g_wqkvT[3 * DMODEL * DMODEL];           // [3072][1024]
__device__ __half g_woutT[DMODEL * DMODEL];               // [1024][1024]
__device__ __half g_qh[BSZ * NH * TSEQ * DK];             // [bh][t][d]
__device__ __half g_kh[BSZ * NH * TSEQ * DK];
__device__ __half g_vh[BSZ * NH * TSEQ * DK];
__device__ __half g_attn[BT * DMODEL];
__device__ float2 g_rope[TSEQ * 32];                      // (cos,sin) per (t, d2)

// swizzle: 64-half rows (128B), 16B chunks
__device__ __forceinline__ unsigned swz(unsigned row, unsigned chunk) {
    return row * 128u + ((chunk ^ (row & 7u)) << 4);
}
__device__ __forceinline__ unsigned smaddr(const void* p) {
    return (unsigned)__cvta_generic_to_shared(p);
}
__device__ __forceinline__ void cp16(unsigned s, const void* g) {
    asm volatile("cp.async.cg.shared.global [%0], [%1], 16;\n" :: "r"(s), "l"(g));
}
__device__ __forceinline__ void cp_commit() { asm volatile("cp.async.commit_group;\n" ::); }
__device__ __forceinline__ void cp_wait0() { asm volatile("cp.async.wait_group 0;\n" ::); }
__device__ __forceinline__ void cp_wait1() { asm volatile("cp.async.wait_group 1;\n" ::); }

__device__ __forceinline__ void ldsm4(unsigned* r, unsigned a) {
    asm volatile("ldmatrix.sync.aligned.m8n8.x4.shared.b16 {%0,%1,%2,%3}, [%4];\n"
                 : "=r"(r[0]), "=r"(r[1]), "=r"(r[2]), "=r"(r[3]) : "r"(a));
}
__device__ __forceinline__ void ldsm4t(unsigned* r, unsigned a) {
    asm volatile("ldmatrix.sync.aligned.m8n8.x4.trans.shared.b16 {%0,%1,%2,%3}, [%4];\n"
                 : "=r"(r[0]), "=r"(r[1]), "=r"(r[2]), "=r"(r[3]) : "r"(a));
}
__device__ __forceinline__ void mma_f16(float* c, unsigned a0, unsigned a1,
                                        unsigned a2, unsigned a3,
                                        unsigned b0, unsigned b1) {
    asm volatile(
        "mma.sync.aligned.m16n8k16.row.col.f32.f16.f16.f32 "
        "{%0,%1,%2,%3}, {%4,%5,%6,%7}, {%8,%9}, {%0,%1,%2,%3};\n"
        : "+f"(c[0]), "+f"(c[1]), "+f"(c[2]), "+f"(c[3])
        : "r"(a0), "r"(a1), "r"(a2), "r"(a3), "r"(b0), "r"(b1));
}
__device__ __forceinline__ unsigned pack_h2(float a, float b) {
    __half2 h = __floats2half2_rn(a, b);
    return *reinterpret_cast<unsigned*>(&h);
}

// ---------------------------------------------------------------------------
// Fused prep: one launch does cast_x + rope table + both weight transposes.
// ---------------------------------------------------------------------------
__global__ __launch_bounds__(256)
void prep_kernel(const float* __restrict__ x,
                 const float* __restrict__ W_qkv,
                 const float* __restrict__ W_out)
{
    __shared__ float tile[64][65];
    const int bid = blockIdx.x;
    const int tid = threadIdx.x;

    if (bid < 4096) {                      // ---- cast x ----
        int i = bid * 256 + tid;           // float4 index
        float4 v = ((const float4*)x)[i];
        __half2 h0 = __floats2half2_rn(v.x, v.y);
        __half2 h1 = __floats2half2_rn(v.z, v.w);
        ((uint2*)g_xh)[i] = make_uint2(*(unsigned*)&h0, *(unsigned*)&h1);
        return;
    }
    if (bid < 4352) {                      // ---- rope table ----
        int i = (bid - 4096) * 256 + tid;  // TSEQ*32
        int tt = i >> 5, d2 = i & 31;
        float invf = exp2f(-(float)(2 * d2) * 0.20762050593046f);
        float s, c;
        sincosf((float)tt * invf, &s, &c);
        g_rope[i] = make_float2(c, s);
        return;
    }

    // ---- weight transpose+cast (64x64 tiles) ----
    const float* W;
    __half* Wt;
    int N, tix;
    if (bid < 5120) { tix = bid - 4352; W = W_qkv; Wt = g_wqkvT; N = 3 * DMODEL; }
    else            { tix = bid - 5120; W = W_out;  Wt = g_woutT; N = DMODEL; }
    const int nt = N / 64;
    const int n0 = (tix % nt) * 64, k0 = (tix / nt) * 64;

    #pragma unroll
    for (int p = 0; p < 4; p++) {
        int j = tid + p * 256;
        int k = j >> 4, c4 = j & 15;
        float4 v = *(const float4*)&W[(size_t)(k0 + k) * N + n0 + c4 * 4];
        tile[k][c4 * 4 + 0] = v.x;
        tile[k][c4 * 4 + 1] = v.y;
        tile[k][c4 * 4 + 2] = v.z;
        tile[k][c4 * 4 + 3] = v.w;
    }
    __syncthreads();
    #pragma unroll
    for (int p = 0; p < 2; p++) {
        int j = tid + p * 256;
        int n = j >> 3, kg = (j & 7) * 8;
        __half hv[8];
        #pragma unroll
        for (int i = 0; i < 8; i++)
            hv[i] = __float2half(tile[kg + i][n]);
        *(uint4*)&Wt[(size_t)(n0 + n) * DMODEL + k0 + kg] = *(uint4*)hv;
    }
}

// ---------------------------------------------------------------------------
// GEMM: 128x128 tile, BK=64, 3-stage cp.async, 8 warps (2x4), warp 64x32.
// NEW: explicit fragment double-buffering across kk (LDSM of kk+1 issued
// before mma of kk) to hide the LDSM->HMMA scoreboard latency.
// mode 0: fp32 C + bias. mode 1: QKV epilogue (bias + RoPE + split, fp16).
// ---------------------------------------------------------------------------
__global__ __launch_bounds__(256, 2)
void gemm_h_kernel(const __half* __restrict__ A, const __half* __restrict__ Bt,
                   const float* __restrict__ bias, float* __restrict__ C,
                   int M, int N, int mode)
{
    extern __shared__ __align__(16) char sm[];
    const int tid = threadIdx.x;
    const int wid = tid >> 5, lane = tid & 31;
    const int g = lane >> 2, t = lane & 3;
    const int bm = blockIdx.y * 128, bn = blockIdx.x * 128;
    const int wm = (wid & 1) * 64, wn = (wid >> 1) * 32;
    const unsigned sbase = smaddr(sm);

    const int lr = tid >> 1;                 // loader row 0..127
    const int lc = (tid & 1) * 4;            // 4 chunks each

    float acc[4][4][4];
    #pragma unroll
    for (int i = 0; i < 4; i++)
        #pragma unroll
        for (int j = 0; j < 4; j++)
            #pragma unroll
            for (int r = 0; r < 4; r++) acc[i][j][r] = 0.f;

    const __half* agp = &A[(size_t)(bm + lr) * 1024 + lc * 8];
    const __half* bgp = &Bt[(size_t)(bn + lr) * 1024 + lc * 8];

    // prologue: stages 0,1
    #pragma unroll
    for (int s = 0; s < 2; s++) {
        unsigned da = sbase + s * 16384, db = sbase + 49152 + s * 16384;
        #pragma unroll
        for (int c = 0; c < 4; c++) {
            cp16(da + swz(lr, lc + c), agp + s * 64 + c * 8);
            cp16(db + swz(lr, lc + c), bgp + s * 64 + c * 8);
        }
        cp_commit();
    }
    cp_wait1();
    __syncthreads();

    const unsigned arow = ((lane >> 3) & 1) * 8 + (lane & 7);
    const unsigned ach  = (lane >> 4);
    const unsigned brow = (lane >> 4) * 8 + (lane & 7);
    const unsigned bch  = (lane >> 3) & 1;

    int buf = 0, bufn = 2;
    #pragma unroll 1
    for (int s = 0; s < GEMM_KT; s++) {
        if (s + 2 < GEMM_KT) {
            unsigned da = sbase + bufn * 16384;
            unsigned db = sbase + 49152 + bufn * 16384;
            const __half* ag = agp + (s + 2) * 64;
            const __half* bg = bgp + (s + 2) * 64;
            #pragma unroll
            for (int c = 0; c < 4; c++) {
                cp16(da + swz(lr, lc + c), ag + c * 8);
                cp16(db + swz(lr, lc + c), bg + c * 8);
            }
            cp_commit();
        }

        const unsigned sa = sbase + buf * 16384;
        const unsigned sb = sbase + 49152 + buf * 16384;

        // fragment double-buffer: preload kk=0, prefetch kk+1 during mma(kk)
        unsigned af[2][4][4], bf[2][2][4];
        #pragma unroll
        for (int mt = 0; mt < 4; mt++)
            ldsm4(af[0][mt], sa + swz(wm + mt * 16 + arow, ach));
        #pragma unroll
        for (int np = 0; np < 2; np++)
            ldsm4(bf[0][np], sb + swz(wn + np * 16 + brow, bch));

        #pragma unroll
        for (int kk = 0; kk < 4; kk++) {
            const int cur = kk & 1, nxt = cur ^ 1;
            if (kk < 3) {
                #pragma unroll
                for (int mt = 0; mt < 4; mt++)
                    ldsm4(af[nxt][mt], sa + swz(wm + mt * 16 + arow, 2 * (kk + 1) + ach));
                #pragma unroll
                for (int np = 0; np < 2; np++)
                    ldsm4(bf[nxt][np], sb + swz(wn + np * 16 + brow, 2 * (kk + 1) + bch));
            }
            #pragma unroll
            for (int mt = 0; mt < 4; mt++)
                #pragma unroll
                for (int nt = 0; nt < 4; nt++)
                    mma_f16(acc[mt][nt],
                            af[cur][mt][0], af[cur][mt][1], af[cur][mt][2], af[cur][mt][3],
                            bf[cur][nt >> 1][(nt & 1) * 2], bf[cur][nt >> 1][(nt & 1) * 2 + 1]);
        }

        if (s + 2 < GEMM_KT)      cp_wait1();
        else if (s + 1 < GEMM_KT) cp_wait0();
        if (s + 1 < GEMM_KT) __syncthreads();

        buf = (buf == 2) ? 0 : buf + 1;
        bufn = (bufn == 2) ? 0 : bufn + 1;
    }

    // ---------------- epilogue ----------------
    if (mode == 0) {
        #pragma unroll
        for (int mt = 0; mt < 4; mt++) {
            int row = bm + wm + mt * 16 + g;
            #pragma unroll
            for (int nt = 0; nt < 4; nt++) {
                int col = bn + wn + nt * 8 + 2 * t;
                float b0 = bias[col], b1 = bias[col + 1];
                *(float2*)&C[(size_t)row * N + col] =
                    make_float2(acc[mt][nt][0] + b0, acc[mt][nt][1] + b1);
                *(float2*)&C[(size_t)(row + 8) * N + col] =
                    make_float2(acc[mt][nt][2] + b0, acc[mt][nt][3] + b1);
            }
        }
    } else {
        #pragma unroll
        for (int nt = 0; nt < 4; nt++) {
            int col = bn + wn + nt * 8 + 2 * t;
            int qi = col >> 10, rem = col & 1023;
            int h = rem >> 6, d0 = rem & 63;
            __half* dst = (qi == 0) ? g_qh : (qi == 1) ? g_kh : g_vh;
            float b0 = bias[col], b1 = bias[col + 1];
            #pragma unroll
            for (int mt = 0; mt < 4; mt++) {
                int row = bm + wm + mt * 16 + g;
                #pragma unroll
                for (int half = 0; half < 2; half++) {
                    int r = row + half * 8;
                    float x1 = acc[mt][nt][half * 2]     + b0;
                    float x2 = acc[mt][nt][half * 2 + 1] + b1;
                    int bb = r >> 11, tr = r & 2047;
                    size_t o = ((size_t)(bb * NH + h) * TSEQ + tr) * DK + d0;
                    if (qi < 2) {
                        float2 cs = g_rope[tr * 32 + (d0 >> 1)];
                        *(__half2*)&dst[o] = __floats2half2_rn(
                            x1 * cs.x - x2 * cs.y, x1 * cs.y + x2 * cs.x);
                    } else {
                        *(__half2*)&dst[o] = __floats2half2_rn(x1, x2);
                    }
                }
            }
        }
    }
}

// ---------------------------------------------------------------------------
// Flash attention (round-12 exact): mma.sync fp32-acc, 2-stage cp.async,
// exp2 softmax, masked-tile skip.
// ---------------------------------------------------------------------------
#define SCL2E 0.18033688011112042f   // (1/8) * log2(e)

__global__ __launch_bounds__(256)
void flash_h_kernel()
{
    extern __shared__ __align__(16) char sm[];
    char* Qs = sm;                               // 16KB (128x64)
    char* Ks[2] = { sm + 16384, sm + 24576 };    // 8KB each (64x64)
    char* Vs[2] = { sm + 32768, sm + 40960 };

    const int tid = threadIdx.x;
    const int wid = tid >> 5, lane = tid & 31;
    const int g = lane >> 2, t = lane & 3;
    const int qx = (TSEQ / 128 - 1) - (blockIdx.x >> 5);  // big tiles first
    const int bh = blockIdx.x & 31;
    const int b = bh >> 4, h = bh & 15;
    const int qb = qx * 128;

    const __half* Qp = g_qh + (size_t)bh * TSEQ * DK;
    const __half* Kp = g_kh + (size_t)bh * TSEQ * DK;
    const __half* Vp = g_vh + (size_t)bh * TSEQ * DK;

    const int lr  = tid >> 1;
    const int lc  = (tid & 1) * 4;
    const int kvr = tid >> 2;
    const int kvc = (tid & 3) * 2;

    {
        unsigned sq = smaddr(Qs);
        #pragma unroll
        for (int c = 0; c < 4; c++)
            cp16(sq + swz(lr, lc + c), &Qp[(size_t)(qb + lr) * DK + (lc + c) * 8]);
        cp_commit();
        unsigned sk = smaddr(Ks[0]), sv = smaddr(Vs[0]);
        #pragma unroll
        for (int c = 0; c < 2; c++) {
            cp16(sk + swz(kvr, kvc + c), &Kp[(size_t)kvr * DK + (kvc + c) * 8]);
            cp16(sv + swz(kvr, kvc + c), &Vp[(size_t)kvr * DK + (kvc + c) * 8]);
        }
        cp_commit();
    }

    unsigned qa[4][4];
    float o[8][4];
    #pragma unroll
    for (int nt = 0; nt < 8; nt++)
        #pragma unroll
        for (int r = 0; r < 4; r++) o[nt][r] = 0.f;
    float m0 = -INFINITY, m1 = -INFINITY, l0 = 0.f, l1 = 0.f;
    const int tiles = 2 * qx + 2;

    const unsigned arow = ((lane >> 3) & 1) * 8 + (lane & 7);
    const unsigned ach  = (lane >> 4);
    const unsigned brow = (lane >> 4) * 8 + (lane & 7);
    const unsigned bch  = (lane >> 3) & 1;

    for (int j = 0; j < tiles; j++) {
        __syncthreads();
        if (j + 1 < tiles) {
            int st = (j + 1) & 1, s0 = (j + 1) * 64;
            unsigned sk = smaddr(Ks[st]), sv = smaddr(Vs[st]);
            #pragma unroll
            for (int c = 0; c < 2; c++) {
                cp16(sk + swz(kvr, kvc + c), &Kp[(size_t)(s0 + kvr) * DK + (kvc + c) * 8]);
                cp16(sv + swz(kvr, kvc + c), &Vp[(size_t)(s0 + kvr) * DK + (kvc + c) * 8]);
            }
            cp_commit();
            cp_wait1();
        } else {
            cp_wait0();
        }
        __syncthreads();

        if (j == 0) {
            unsigned sq = smaddr(Qs);
            #pragma unroll
            for (int kk = 0; kk < 4; kk++)
                ldsm4(qa[kk], sq + swz(wid * 16 + arow, 2 * kk + ach));
        }

        // Fully-masked tile for upper warps: P == 0, state provably unchanged.
        if (j == 2 * qx + 1 && wid < 4) continue;

        const unsigned sk = smaddr(Ks[j & 1]), sv = smaddr(Vs[j & 1]);

        float sa[8][4];
        #pragma unroll
        for (int nt = 0; nt < 8; nt++)
            #pragma unroll
            for (int r = 0; r < 4; r++) sa[nt][r] = 0.f;
        #pragma unroll
        for (int kk = 0; kk < 4; kk++) {
            unsigned kf[4][4];
            #pragma unroll
            for (int np = 0; np < 4; np++)
                ldsm4(kf[np], sk + swz(np * 16 + brow, 2 * kk + bch));
            #pragma unroll
            for (int nt = 0; nt < 8; nt++)
                mma_f16(sa[nt], qa[kk][0], qa[kk][1], qa[kk][2], qa[kk][3],
                        kf[nt >> 1][(nt & 1) * 2], kf[nt >> 1][(nt & 1) * 2 + 1]);
        }

        // mask only where the warp strip straddles the diagonal
        if ((j == 2 * qx && wid < 4) || (j == 2 * qx + 1 && wid >= 4)) {
            int row0 = qb + wid * 16 + g, row1 = row0 + 8;
            #pragma unroll
            for (int nt = 0; nt < 8; nt++) {
                int c = j * 64 + nt * 8 + 2 * t;
                if (c > row0)     sa[nt][0] = -1e30f;
                if (c + 1 > row0) sa[nt][1] = -1e30f;
                if (c > row1)     sa[nt][2] = -1e30f;
                if (c + 1 > row1) sa[nt][3] = -1e30f;
            }
        }

        float rm0 = -INFINITY, rm1 = -INFINITY;
        #pragma unroll
        for (int nt = 0; nt < 8; nt++) {
            rm0 = fmaxf(rm0, fmaxf(sa[nt][0], sa[nt][1]));
            rm1 = fmaxf(rm1, fmaxf(sa[nt][2], sa[nt][3]));
        }
        rm0 = fmaxf(rm0, __shfl_xor_sync(0xffffffffu, rm0, 1));
        rm0 = fmaxf(rm0, __shfl_xor_sync(0xffffffffu, rm0, 2));
        rm1 = fmaxf(rm1, __shfl_xor_sync(0xffffffffu, rm1, 1));
        rm1 = fmaxf(rm1, __shfl_xor_sync(0xffffffffu, rm1, 2));

        float M0 = fmaxf(m0, rm0), M1 = fmaxf(m1, rm1);
        float a0 = exp2f((m0 - M0) * SCL2E);
        float a1 = exp2f((m1 - M1) * SCL2E);
        float M0s = M0 * SCL2E, M1s = M1 * SCL2E;

        unsigned pa[8], pb[8];
        float rs0 = 0.f, rs1 = 0.f;
        #pragma unroll
        for (int nt = 0; nt < 8; nt++) {
            float p00 = exp2f(fmaf(sa[nt][0], SCL2E, -M0s));
            float p01 = exp2f(fmaf(sa[nt][1], SCL2E, -M0s));
            float p10 = exp2f(fmaf(sa[nt][2], SCL2E, -M1s));
            float p11 = exp2f(fmaf(sa[nt][3], SCL2E, -M1s));
            rs0 += p00 + p01;
            rs1 += p10 + p11;
            pa[nt] = pack_h2(p00, p01);
            pb[nt] = pack_h2(p10, p11);
        }
        rs0 += __shfl_xor_sync(0xffffffffu, rs0, 1);
        rs0 += __shfl_xor_sync(0xffffffffu, rs0, 2);
        rs1 += __shfl_xor_sync(0xffffffffu, rs1, 1);
        rs1 += __shfl_xor_sync(0xffffffffu, rs1, 2);
        l0 = l0 * a0 + rs0;
        l1 = l1 * a1 + rs1;
        m0 = M0; m1 = M1;

        #pragma unroll
        for (int nt = 0; nt < 8; nt++) {
            o[nt][0] *= a0; o[nt][1] *= a0;
            o[nt][2] *= a1; o[nt][3] *= a1;
        }

        #pragma unroll
        for (int kk = 0; kk < 4; kk++) {
            unsigned vf[4][4];
            #pragma unroll
            for (int np = 0; np < 4; np++)
                ldsm4t(vf[np], sv + swz(16 * kk + arow, np * 2 + ach));
            unsigned A0 = pa[2 * kk], A1 = pb[2 * kk];
            unsigned A2 = pa[2 * kk + 1], A3 = pb[2 * kk + 1];
            #pragma unroll
            for (int nt = 0; nt < 8; nt++)
                mma_f16(o[nt], A0, A1, A2, A3,
                        vf[nt >> 1][(nt & 1) * 2], vf[nt >> 1][(nt & 1) * 2 + 1]);
        }
    }

    float i0 = 1.f / l0, i1 = 1.f / l1;
    int row0 = qb + wid * 16 + g;
    size_t gr0 = (size_t)(b * TSEQ + row0) * DMODEL;
    size_t gr1 = (size_t)(b * TSEQ + row0 + 8) * DMODEL;
    #pragma unroll
    for (int nt = 0; nt < 8; nt++) {
        int col = h * DK + nt * 8 + 2 * t;
        *(__half2*)&g_attn[gr0 + col] = __floats2half2_rn(o[nt][0] * i0, o[nt][1] * i0);
        *(__half2*)&g_attn[gr1 + col] = __floats2half2_rn(o[nt][2] * i1, o[nt][3] * i1);
    }
}

// ---------------------------------------------------------------------------
extern "C" void kernel_launch(void* const* d_in, const int* in_sizes, int n_in,
                              void* d_out, int out_size)
{
    const float* x     = (const float*)d_in[0];
    const float* W_qkv = (const float*)d_in[1];
    const float* b_qkv = (const float*)d_in[2];
    const float* W_out = (const float*)d_in[3];
    const float* b_out = (const float*)d_in[4];
    float* out = (float*)d_out;

    __half* xh;     cudaGetSymbolAddress((void**)&xh,     g_xh);
    __half* wqkvT;  cudaGetSymbolAddress((void**)&wqkvT,  g_wqkvT);
    __half* woutT;  cudaGetSymbolAddress((void**)&woutT,  g_woutT);
    __half* attn;   cudaGetSymbolAddress((void**)&attn,   g_attn);

    const int gemm_smem = 98304;   // 3 x (16K A + 16K B)
    cudaFuncSetAttribute(gemm_h_kernel,
                         cudaFuncAttributeMaxDynamicSharedMemorySize, gemm_smem);
    cudaFuncSetAttribute(flash_h_kernel,
                         cudaFuncAttributeMaxDynamicSharedMemorySize, 49152);

    // 0) fused prep (cast x, rope table, both weight transposes)
    prep_kernel<<<5376, 256>>>(x, W_qkv, W_out);

    // 1) QKV projection + fused bias/RoPE/split (mode 1)
    {
        dim3 grid(3 * DMODEL / 128, BT / 128);
        gemm_h_kernel<<<grid, 256, gemm_smem>>>(xh, wqkvT, b_qkv, nullptr,
                                                BT, 3 * DMODEL, 1);
    }

    // 2) flash attention (global big-first ordering)
    flash_h_kernel<<<(TSEQ / 128) * BSZ * NH, 256, 49152>>>();

    // 3) output projection (mode 0) -> d_out
    {
        dim3 grid(DMODEL / 128, BT / 128);
        gemm_h_kernel<<<grid, 256, gemm_smem>>>(attn, woutT, b_out, out,
                                                BT, DMODEL, 0);
    }
}